// round 13
// baseline (speedup 1.0000x reference)
#include <cuda_runtime.h>
#include <cuda_bf16.h>
#include <cstdint>

#define NPTS 16384
#define NW   512          // words per adjacency row
#define NT   512          // row tiles (NPTS/32)
#define EPS2 0.04f
#define MINPTS 10
#define BIGV NPTS

// -------- scratch (static device globals; no allocation) --------
// tile-major adjacency: ADJ(rt, w, l) = g_adj[(rt*512 + w)*32 + l], row = rt*32+l
__device__ unsigned g_adj[(size_t)NT * NW * 32];   // 33.5 MB
__device__ unsigned g_corebits[NW];
__device__ int      g_core[NPTS];
__device__ int      g_parent[NPTS];
__device__ unsigned short g_lab16[NPTS];
__device__ int      g_root[NPTS];
__device__ int      g_rank[NPTS];

// ---------------- f32x2 packed helpers ----------------
typedef unsigned long long u64;
__device__ __forceinline__ u64 pack2(float lo, float hi) {
    u64 r; asm("mov.b64 %0, {%1, %2};" : "=l"(r) : "f"(lo), "f"(hi)); return r;
}
__device__ __forceinline__ u64 mul2(u64 a, u64 b) {
    u64 d; asm("mul.rn.f32x2 %0, %1, %2;" : "=l"(d) : "l"(a), "l"(b)); return d;
}
__device__ __forceinline__ u64 add2(u64 a, u64 b) {
    u64 d; asm("add.rn.f32x2 %0, %1, %2;" : "=l"(d) : "l"(a), "l"(b)); return d;
}

// ---------------- 32x32 bit-matrix transpose (warp) ----------------
__device__ __forceinline__ unsigned bittranspose(unsigned x, int lane) {
    const unsigned msk[5] = {0xFFFF0000u, 0xFF00FF00u, 0xF0F0F0F0u, 0xCCCCCCCCu, 0xAAAAAAAAu};
#pragma unroll
    for (int k = 0; k < 5; k++) {
        int s = 16 >> k;
        unsigned m = msk[k];
        unsigned y = __shfl_xor_sync(0xffffffffu, x, s);
        if ((lane & s) == 0) x = (x & ~m) | ((y << s) & m);
        else                 x = (x &  m) | ((y >> s) & ~m);
    }
    return x;
}

// ---------------- k1: triangular adjacency with mirror-transpose ----------------
// grid 1024 x 128 threads (4 warps). block b: pair p=b>>2, quarter qd=b&3.
// tiles tA=p, tB=511-p; warp w handles chunk residues (qd*4+w) mod 16.
// lane = row within tile; row constants (-2x,-2y,-2z,sq) packed in registers.
struct RowPack { u64 x2, y2, z2, s2; };

__device__ __forceinline__ RowPack load_rowpack(const float* __restrict__ pts, int r) {
    float x = pts[3*r], y = pts[3*r+1], z = pts[3*r+2];
    float s = __fadd_rn(__fadd_rn(__fmul_rn(x,x), __fmul_rn(y,y)), __fmul_rn(z,z));
    float xn = __fmul_rn(-2.0f, x);
    float yn = __fmul_rn(-2.0f, y);
    float zn = __fmul_rn(-2.0f, z);
    RowPack rp;
    rp.x2 = pack2(xn, xn); rp.y2 = pack2(yn, yn); rp.z2 = pack2(zn, zn); rp.s2 = pack2(s, s);
    return rp;
}

__device__ __forceinline__ unsigned tile_word(const RowPack& rp, const u64* __restrict__ sj,
                                              u64 negeps) {
    unsigned wrd = 0;
#pragma unroll
    for (int q = 0; q < 16; q++) {
        const u64* e = sj + q*4;
        u64 jx = e[0], jy = e[1], jz = e[2], js = e[3];
        u64 dotn = add2(add2(mul2(rp.x2, jx), mul2(rp.y2, jy)), mul2(rp.z2, jz));
        u64 d2   = add2(add2(rp.s2, js), dotn);
        u64 v    = add2(d2, negeps);          // sign bit <=> d2 < EPS2 (exact for strict <)
        unsigned lo, hi;
        asm("mov.b64 {%0, %1}, %2;" : "=r"(lo), "=r"(hi) : "l"(v));
        wrd |= (lo >> 31) << (2*q);
        wrd |= (hi >> 31) << (2*q + 1);
    }
    return wrd;
}

__global__ void __launch_bounds__(128) k1_adj(const float* __restrict__ pts) {
    __shared__ __align__(16) u64 sj[4][16][4];   // [warp][q][x2,y2,z2,s2]
    const int w    = threadIdx.x >> 5;
    const int lane = threadIdx.x & 31;
    const int p  = blockIdx.x >> 2;
    const int qd = blockIdx.x & 3;
    const int tA = p, tB = (NT - 1) - p;
    const u64 negeps = pack2(-EPS2, -EPS2);

    RowPack ra = load_rowpack(pts, tA*32 + lane);
    RowPack rb = load_rowpack(pts, tB*32 + lane);

    for (int jc = qd*4 + w; jc <= tB; jc += 16) {
        // ---- stage 32 j points as packed pairs (lanes 0..15, 2 points each) ----
        if (lane < 16) {
            int j0 = jc*32 + 2*lane;
            const float2* pp = (const float2*)(pts + 3*j0);
            float2 a = pp[0], b = pp[1], c = pp[2];
            // x0=a.x y0=a.y z0=b.x | x1=b.y y1=c.x z1=c.y
            float s0 = __fadd_rn(__fadd_rn(__fmul_rn(a.x,a.x), __fmul_rn(a.y,a.y)), __fmul_rn(b.x,b.x));
            float s1 = __fadd_rn(__fadd_rn(__fmul_rn(b.y,b.y), __fmul_rn(c.x,c.x)), __fmul_rn(c.y,c.y));
            u64* dst = sj[w][lane];
            dst[0] = pack2(a.x, b.y);
            dst[1] = pack2(a.y, c.x);
            dst[2] = pack2(b.x, c.y);
            dst[3] = pack2(s0, s1);
        }
        __syncwarp();

        unsigned wB = tile_word(rb, &sj[w][0][0], negeps);
        g_adj[(((tB << 9) + jc) << 5) + lane] = wB;
        if (jc < tB) {
            unsigned tw = bittranspose(wB, lane);
            g_adj[(((jc << 9) + tB) << 5) + lane] = tw;
        }
        if (jc <= tA) {
            unsigned wA = tile_word(ra, &sj[w][0][0], negeps);
            g_adj[(((tA << 9) + jc) << 5) + lane] = wA;
            if (jc < tA) {
                unsigned tw = bittranspose(wA, lane);
                g_adj[(((jc << 9) + tA) << 5) + lane] = tw;
            }
        }
        __syncwarp();
    }
}

// ---------------- k1b: degree/core + init (MLP-8 popc pass) ----------------
__global__ void __launch_bounds__(256) k1b_deg() {
    __shared__ int part[8][32];
    int rt = blockIdx.x;
    int lane = threadIdx.x & 31, sl = threadIdx.x >> 5;
    const unsigned* basep = g_adj + ((size_t)rt << 14);
    int cnt = 0;
    for (int wi0 = sl; wi0 < NW; wi0 += 64) {
        unsigned wb[8];
#pragma unroll
        for (int u = 0; u < 8; u++) wb[u] = basep[((wi0 + u*8) << 5) + lane];
#pragma unroll
        for (int u = 0; u < 8; u++) cnt += __popc(wb[u]);
    }
    part[sl][lane] = cnt;
    __syncthreads();
    if (threadIdx.x < 32) {
        int deg = 0;
#pragma unroll
        for (int s = 0; s < 8; s++) deg += part[s][lane];
        int row = (rt << 5) + lane;
        int c = (deg >= MINPTS) ? 1 : 0;
        g_core[row]   = c;
        g_parent[row] = row;
        unsigned cb = __ballot_sync(0xffffffffu, c != 0);
        if (lane == 0) g_corebits[rt] = cb;
    }
}

// ---------------- union-find (hook larger root under smaller =>
//                  final root of each component is its minimum index) ----------------
__device__ __forceinline__ int pload(int x) { return __ldcg(&g_parent[x]); }  // L2-coherent

__device__ __forceinline__ int uf_find(int x) {
    int pr = pload(x);
    while (pr != x) {
        int gp = pload(pr);
        if (gp != pr) g_parent[x] = gp;   // path halving; benign race
        x = pr;
        pr = gp;
    }
    return pr;
}

__device__ __forceinline__ void uf_union(int a, int b) {
    int ra = uf_find(a), rb = uf_find(b);
    while (ra != rb) {
        if (ra > rb) { int t = ra; ra = rb; rb = t; }
        int old = atomicCAS(&g_parent[rb], rb, ra);
        if (old == rb) return;
        rb = uf_find(old);
        ra = uf_find(ra);
    }
}

// ---------------- k2: unions over core-core edges (strictly lower triangle) ----------------
__global__ void __launch_bounds__(256) k2_union() {
    __shared__ unsigned scb[NW];
    int lane = threadIdx.x & 31, sl = threadIdx.x >> 5;
    for (int i = threadIdx.x; i < NW; i += 256) scb[i] = g_corebits[i];
    __syncthreads();

    int rt = (NT - 1) - blockIdx.x;          // biggest row-tiles first
    int row = (rt << 5) + lane;
    if (!g_core[row]) return;
    const unsigned* basep = g_adj + ((size_t)rt << 14);
    for (int wi0 = sl; wi0 <= rt; wi0 += 64) {
        unsigned wb[8];
#pragma unroll
        for (int u = 0; u < 8; u++) {
            int wi = wi0 + u*8;
            wb[u] = (wi <= rt) ? (basep[(wi << 5) + lane] & scb[wi]) : 0u;
        }
#pragma unroll
        for (int u = 0; u < 8; u++) {
            int wi = wi0 + u*8;
            unsigned word = wb[u];
            if (wi == rt) word &= (1u << lane) - 1u;   // j < row on diagonal tile
            while (word) {
                int b = __ffs(word) - 1;
                word &= word - 1u;
                uf_union(row, (wi << 5) + b);
            }
        }
    }
}

// ---------------- k4: flatten labels to u16 (root == component min < 16384) ----------------
__global__ void k4_flat() {
    int i = blockIdx.x * blockDim.x + threadIdx.x;
    if (i >= NPTS) return;
    g_lab16[i] = g_core[i] ? (unsigned short)uf_find(i) : (unsigned short)0xFFFF;
}

// ---------------- k5: per-point min label among core neighbors (smem table) ----------------
__global__ void __launch_bounds__(256) k5_border() {
    __shared__ unsigned short slab[NPTS];    // 32 KB flattened labels
    __shared__ unsigned scb[NW];
    __shared__ int part[8][32];
    int lane = threadIdx.x & 31, sl = threadIdx.x >> 5;

    {   // stage labels (coalesced uint4) + corebits
        const uint4* src = (const uint4*)g_lab16;
        uint4* dst = (uint4*)slab;
        for (int i = threadIdx.x; i < NPTS/8; i += 256) dst[i] = src[i];
        for (int i = threadIdx.x; i < NW; i += 256) scb[i] = g_corebits[i];
    }
    __syncthreads();

    int rt = blockIdx.x;
    const unsigned* basep = g_adj + ((size_t)rt << 14);
    int mn = 0xFFFF;
    for (int wi0 = sl; wi0 < NW; wi0 += 64) {
        unsigned wb[8];
#pragma unroll
        for (int u = 0; u < 8; u++) wb[u] = basep[((wi0 + u*8) << 5) + lane];
#pragma unroll
        for (int u = 0; u < 8; u++) {
            unsigned word = wb[u] & scb[wi0 + u*8];
            int jb = (wi0 + u*8) << 5;
            while (word) {
                int b = __ffs(word) - 1;
                word &= word - 1u;
                mn = min(mn, (int)slab[jb + b]);
            }
        }
    }
    part[sl][lane] = mn;
    __syncthreads();
    if (threadIdx.x < 32) {
        int m = part[0][lane];
#pragma unroll
        for (int s = 1; s < 8; s++) m = min(m, part[s][lane]);
        g_root[(rt << 5) + lane] = (m == 0xFFFF) ? BIGV : m;
    }
}

// ---------------- k6: rank scan (renumber roots) + final labels ----------------
__global__ void __launch_bounds__(512) k6_finish(float* __restrict__ out) {
    __shared__ int ssum[512];
    int t = threadIdx.x;                 // 512 threads x 32 elements
    int base = t * 32;
    int cnt = 0;
#pragma unroll
    for (int k = 0; k < 32; k++) {
        int i = base + k;
        cnt += (g_core[i] && g_parent[i] == i) ? 1 : 0;   // component root
    }
    ssum[t] = cnt;
    __syncthreads();
    for (int o = 1; o < 512; o <<= 1) {
        int v = (t >= o) ? ssum[t - o] : 0;
        __syncthreads();
        ssum[t] += v;
        __syncthreads();
    }
    int run = (t > 0) ? ssum[t - 1] : 0;
#pragma unroll
    for (int k = 0; k < 32; k++) {
        int i = base + k;
        run += (g_core[i] && g_parent[i] == i) ? 1 : 0;
        g_rank[i] = run - 1;             // inclusive cumsum - 1
    }
    __syncthreads();
#pragma unroll
    for (int k = 0; k < 32; k++) {
        int i = base + k;
        int r = g_root[i];
        out[i] = (r < BIGV) ? (float)g_rank[r] : -1.0f;
    }
}

// ---------------- launch ----------------
extern "C" void kernel_launch(void* const* d_in, const int* in_sizes, int n_in,
                              void* d_out, int out_size) {
    const float* pts = (const float*)d_in[0];
    float* out = (float*)d_out;
    (void)in_sizes; (void)n_in; (void)out_size;

    k1_adj    <<<NT * 2, 128>>>(pts);    // 1024 blocks: pair quarters
    k1b_deg   <<<NT, 256>>>();
    k2_union  <<<NT, 256>>>();
    k4_flat   <<<NPTS / 256, 256>>>();
    k5_border <<<NT, 256>>>();
    k6_finish <<<1, 512>>>(out);
}

// round 14
// speedup vs baseline: 1.0125x; 1.0125x over previous
#include <cuda_runtime.h>
#include <cuda_bf16.h>
#include <cstdint>

#define NPTS 16384
#define NW   512          // words per adjacency row
#define NT   512          // row tiles (NPTS/32)
#define EPS2 0.04f
#define MINPTS 10
#define BIGV NPTS

// -------- scratch (static device globals; no allocation) --------
// tile-major adjacency: ADJ(rt, w, l) = g_adj[(rt*512 + w)*32 + l], row = rt*32+l
__device__ unsigned g_adj[(size_t)NT * NW * 32];   // 33.5 MB
__device__ unsigned g_corebits[NW];
__device__ int      g_core[NPTS];
__device__ int      g_parent[NPTS];
__device__ unsigned short g_lab16[NPTS];
__device__ int      g_root[NPTS];
__device__ int      g_rank[NPTS];

// ---------------- f32x2 packed helpers ----------------
typedef unsigned long long u64;
__device__ __forceinline__ u64 pack2(float lo, float hi) {
    u64 r; asm("mov.b64 %0, {%1, %2};" : "=l"(r) : "f"(lo), "f"(hi)); return r;
}
__device__ __forceinline__ u64 mul2(u64 a, u64 b) {
    u64 d; asm("mul.rn.f32x2 %0, %1, %2;" : "=l"(d) : "l"(a), "l"(b)); return d;
}
__device__ __forceinline__ u64 add2(u64 a, u64 b) {
    u64 d; asm("add.rn.f32x2 %0, %1, %2;" : "=l"(d) : "l"(a), "l"(b)); return d;
}

// ---------------- 32x32 bit-matrix transpose (warp) ----------------
__device__ __forceinline__ unsigned bittranspose(unsigned x, int lane) {
    const unsigned msk[5] = {0xFFFF0000u, 0xFF00FF00u, 0xF0F0F0F0u, 0xCCCCCCCCu, 0xAAAAAAAAu};
#pragma unroll
    for (int k = 0; k < 5; k++) {
        int s = 16 >> k;
        unsigned m = msk[k];
        unsigned y = __shfl_xor_sync(0xffffffffu, x, s);
        if ((lane & s) == 0) x = (x & ~m) | ((y << s) & m);
        else                 x = (x &  m) | ((y >> s) & ~m);
    }
    return x;
}

// ---------------- k1: triangular adjacency with mirror-transpose ----------------
// grid 1024 x 128 threads (4 warps). block b: pair p=b>>2, quarter qd=b&3.
// tiles tA=p, tB=511-p; warp w handles chunk residues (qd*4+w) mod 16.
// lane = row within tile; row constants (-2x,-2y,-2z,sq) packed in registers.
struct RowPack { u64 x2, y2, z2, s2; };

__device__ __forceinline__ RowPack load_rowpack(const float* __restrict__ pts, int r) {
    float x = pts[3*r], y = pts[3*r+1], z = pts[3*r+2];
    float s = __fadd_rn(__fadd_rn(__fmul_rn(x,x), __fmul_rn(y,y)), __fmul_rn(z,z));
    float xn = __fmul_rn(-2.0f, x);
    float yn = __fmul_rn(-2.0f, y);
    float zn = __fmul_rn(-2.0f, z);
    RowPack rp;
    rp.x2 = pack2(xn, xn); rp.y2 = pack2(yn, yn); rp.z2 = pack2(zn, zn); rp.s2 = pack2(s, s);
    return rp;
}

__device__ __forceinline__ unsigned tile_word(const RowPack& rp, const u64* __restrict__ sj,
                                              u64 negeps) {
    unsigned wrd = 0;
#pragma unroll
    for (int q = 0; q < 16; q++) {
        const u64* e = sj + q*4;
        u64 jx = e[0], jy = e[1], jz = e[2], js = e[3];
        u64 dotn = add2(add2(mul2(rp.x2, jx), mul2(rp.y2, jy)), mul2(rp.z2, jz));
        u64 d2   = add2(add2(rp.s2, js), dotn);
        u64 v    = add2(d2, negeps);          // sign bit <=> d2 < EPS2 (exact for strict <)
        unsigned lo, hi;
        asm("mov.b64 {%0, %1}, %2;" : "=r"(lo), "=r"(hi) : "l"(v));
        wrd |= (lo >> 31) << (2*q);
        wrd |= (hi >> 31) << (2*q + 1);
    }
    return wrd;
}

__global__ void __launch_bounds__(128) k1_adj(const float* __restrict__ pts) {
    __shared__ __align__(16) u64 sj[4][16][4];   // [warp][q][x2,y2,z2,s2]
    const int w    = threadIdx.x >> 5;
    const int lane = threadIdx.x & 31;
    const int p  = blockIdx.x >> 2;
    const int qd = blockIdx.x & 3;
    const int tA = p, tB = (NT - 1) - p;
    const u64 negeps = pack2(-EPS2, -EPS2);

    RowPack ra = load_rowpack(pts, tA*32 + lane);
    RowPack rb = load_rowpack(pts, tB*32 + lane);

    for (int jc = qd*4 + w; jc <= tB; jc += 16) {
        // ---- stage 32 j points as packed pairs (lanes 0..15, 2 points each) ----
        if (lane < 16) {
            int j0 = jc*32 + 2*lane;
            const float2* pp = (const float2*)(pts + 3*j0);
            float2 a = pp[0], b = pp[1], c = pp[2];
            // x0=a.x y0=a.y z0=b.x | x1=b.y y1=c.x z1=c.y
            float s0 = __fadd_rn(__fadd_rn(__fmul_rn(a.x,a.x), __fmul_rn(a.y,a.y)), __fmul_rn(b.x,b.x));
            float s1 = __fadd_rn(__fadd_rn(__fmul_rn(b.y,b.y), __fmul_rn(c.x,c.x)), __fmul_rn(c.y,c.y));
            u64* dst = sj[w][lane];
            dst[0] = pack2(a.x, b.y);
            dst[1] = pack2(a.y, c.x);
            dst[2] = pack2(b.x, c.y);
            dst[3] = pack2(s0, s1);
        }
        __syncwarp();

        unsigned wB = tile_word(rb, &sj[w][0][0], negeps);
        g_adj[(((tB << 9) + jc) << 5) + lane] = wB;
        if (jc < tB) {
            unsigned tw = bittranspose(wB, lane);
            g_adj[(((jc << 9) + tB) << 5) + lane] = tw;
        }
        if (jc <= tA) {
            unsigned wA = tile_word(ra, &sj[w][0][0], negeps);
            g_adj[(((tA << 9) + jc) << 5) + lane] = wA;
            if (jc < tA) {
                unsigned tw = bittranspose(wA, lane);
                g_adj[(((jc << 9) + tA) << 5) + lane] = tw;
            }
        }
        __syncwarp();
    }
}

// ---------------- k1b: degree/core + init (MLP-8 popc pass) ----------------
__global__ void __launch_bounds__(256) k1b_deg() {
    __shared__ int part[8][32];
    int rt = blockIdx.x;
    int lane = threadIdx.x & 31, sl = threadIdx.x >> 5;
    const unsigned* basep = g_adj + ((size_t)rt << 14);
    int cnt = 0;
    for (int wi0 = sl; wi0 < NW; wi0 += 64) {
        unsigned wb[8];
#pragma unroll
        for (int u = 0; u < 8; u++) wb[u] = basep[((wi0 + u*8) << 5) + lane];
#pragma unroll
        for (int u = 0; u < 8; u++) cnt += __popc(wb[u]);
    }
    part[sl][lane] = cnt;
    __syncthreads();
    if (threadIdx.x < 32) {
        int deg = 0;
#pragma unroll
        for (int s = 0; s < 8; s++) deg += part[s][lane];
        int row = (rt << 5) + lane;
        int c = (deg >= MINPTS) ? 1 : 0;
        g_core[row]   = c;
        g_parent[row] = row;
        unsigned cb = __ballot_sync(0xffffffffu, c != 0);
        if (lane == 0) g_corebits[rt] = cb;
    }
}

// ---------------- union-find (hook larger root under smaller =>
//                  final root of each component is its minimum index) ----------------
__device__ __forceinline__ int pload(int x) { return __ldcg(&g_parent[x]); }  // L2-coherent

__device__ __forceinline__ int uf_find(int x) {
    int pr = pload(x);
    while (pr != x) {
        int gp = pload(pr);
        if (gp != pr) g_parent[x] = gp;   // path halving; benign race
        x = pr;
        pr = gp;
    }
    return pr;
}

__device__ __forceinline__ void uf_union(int a, int b) {
    int ra = uf_find(a), rb = uf_find(b);
    while (ra != rb) {
        if (ra > rb) { int t = ra; ra = rb; rb = t; }
        int old = atomicCAS(&g_parent[rb], rb, ra);
        if (old == rb) return;
        rb = uf_find(old);
        ra = uf_find(ra);
    }
}

// ---------------- k2: unions over core-core edges (strictly lower triangle) ----------------
__global__ void __launch_bounds__(256) k2_union() {
    __shared__ unsigned scb[NW];
    int lane = threadIdx.x & 31, sl = threadIdx.x >> 5;
    for (int i = threadIdx.x; i < NW; i += 256) scb[i] = g_corebits[i];
    __syncthreads();

    int rt = (NT - 1) - blockIdx.x;          // biggest row-tiles first
    int row = (rt << 5) + lane;
    if (!g_core[row]) return;
    const unsigned* basep = g_adj + ((size_t)rt << 14);
    for (int wi0 = sl; wi0 <= rt; wi0 += 64) {
        unsigned wb[8];
#pragma unroll
        for (int u = 0; u < 8; u++) {
            int wi = wi0 + u*8;
            wb[u] = (wi <= rt) ? (basep[(wi << 5) + lane] & scb[wi]) : 0u;
        }
#pragma unroll
        for (int u = 0; u < 8; u++) {
            int wi = wi0 + u*8;
            unsigned word = wb[u];
            if (wi == rt) word &= (1u << lane) - 1u;   // j < row on diagonal tile
            while (word) {
                int b = __ffs(word) - 1;
                word &= word - 1u;
                uf_union(row, (wi << 5) + b);
            }
        }
    }
}

// ---------------- k4: flatten labels to u16 (root == component min < 16384) ----------------
__global__ void k4_flat() {
    int i = blockIdx.x * blockDim.x + threadIdx.x;
    if (i >= NPTS) return;
    g_lab16[i] = g_core[i] ? (unsigned short)uf_find(i) : (unsigned short)0xFFFF;
}

// ---------------- k5: per-point min label among core neighbors (smem table) ----------------
__global__ void __launch_bounds__(256) k5_border() {
    __shared__ unsigned short slab[NPTS];    // 32 KB flattened labels
    __shared__ unsigned scb[NW];
    __shared__ int part[8][32];
    int lane = threadIdx.x & 31, sl = threadIdx.x >> 5;

    {   // stage labels (coalesced uint4) + corebits
        const uint4* src = (const uint4*)g_lab16;
        uint4* dst = (uint4*)slab;
        for (int i = threadIdx.x; i < NPTS/8; i += 256) dst[i] = src[i];
        for (int i = threadIdx.x; i < NW; i += 256) scb[i] = g_corebits[i];
    }
    __syncthreads();

    int rt = blockIdx.x;
    const unsigned* basep = g_adj + ((size_t)rt << 14);
    int mn = 0xFFFF;
    for (int wi0 = sl; wi0 < NW; wi0 += 64) {
        unsigned wb[8];
#pragma unroll
        for (int u = 0; u < 8; u++) wb[u] = basep[((wi0 + u*8) << 5) + lane];
#pragma unroll
        for (int u = 0; u < 8; u++) {
            unsigned word = wb[u] & scb[wi0 + u*8];
            int jb = (wi0 + u*8) << 5;
            while (word) {
                int b = __ffs(word) - 1;
                word &= word - 1u;
                mn = min(mn, (int)slab[jb + b]);
            }
        }
    }
    part[sl][lane] = mn;
    __syncthreads();
    if (threadIdx.x < 32) {
        int m = part[0][lane];
#pragma unroll
        for (int s = 1; s < 8; s++) m = min(m, part[s][lane]);
        g_root[(rt << 5) + lane] = (m == 0xFFFF) ? BIGV : m;
    }
}

// ---------------- k6: rank scan (renumber roots) + final labels ----------------
__global__ void __launch_bounds__(512) k6_finish(float* __restrict__ out) {
    __shared__ int ssum[512];
    int t = threadIdx.x;                 // 512 threads x 32 elements
    int base = t * 32;
    int cnt = 0;
#pragma unroll
    for (int k = 0; k < 32; k++) {
        int i = base + k;
        cnt += (g_core[i] && g_parent[i] == i) ? 1 : 0;   // component root
    }
    ssum[t] = cnt;
    __syncthreads();
    for (int o = 1; o < 512; o <<= 1) {
        int v = (t >= o) ? ssum[t - o] : 0;
        __syncthreads();
        ssum[t] += v;
        __syncthreads();
    }
    int run = (t > 0) ? ssum[t - 1] : 0;
#pragma unroll
    for (int k = 0; k < 32; k++) {
        int i = base + k;
        run += (g_core[i] && g_parent[i] == i) ? 1 : 0;
        g_rank[i] = run - 1;             // inclusive cumsum - 1
    }
    __syncthreads();
#pragma unroll
    for (int k = 0; k < 32; k++) {
        int i = base + k;
        int r = g_root[i];
        out[i] = (r < BIGV) ? (float)g_rank[r] : -1.0f;
    }
}

// ---------------- launch ----------------
extern "C" void kernel_launch(void* const* d_in, const int* in_sizes, int n_in,
                              void* d_out, int out_size) {
    const float* pts = (const float*)d_in[0];
    float* out = (float*)d_out;
    (void)in_sizes; (void)n_in; (void)out_size;

    k1_adj    <<<NT * 2, 128>>>(pts);    // 1024 blocks: pair quarters
    k1b_deg   <<<NT, 256>>>();
    k2_union  <<<NT, 256>>>();
    k4_flat   <<<NPTS / 256, 256>>>();
    k5_border <<<NT, 256>>>();
    k6_finish <<<1, 512>>>(out);
}

// round 15
// speedup vs baseline: 1.0743x; 1.0610x over previous
#include <cuda_runtime.h>
#include <cuda_bf16.h>
#include <cstdint>

#define NPTS 16384
#define NW   512          // words per adjacency row
#define NT   512          // row tiles (NPTS/32)
#define EPS2 0.04f
#define MINPTS 10
#define BIGV NPTS

// -------- scratch (static device globals; no allocation) --------
// tile-major adjacency: ADJ(rt, w, l) = g_adj[(rt*512 + w)*32 + l], row = rt*32+l
__device__ unsigned g_adj[(size_t)NT * NW * 32];   // 33.5 MB
__device__ unsigned g_corebits[NW];
__device__ int      g_core[NPTS];
__device__ int      g_parent[NPTS];
__device__ unsigned short g_lab16[NPTS];
__device__ int      g_root[NPTS];
__device__ int      g_rank[NPTS];

// ---------------- f32x2 packed helpers ----------------
typedef unsigned long long u64;
__device__ __forceinline__ u64 pack2(float lo, float hi) {
    u64 r; asm("mov.b64 %0, {%1, %2};" : "=l"(r) : "f"(lo), "f"(hi)); return r;
}
__device__ __forceinline__ u64 mul2(u64 a, u64 b) {
    u64 d; asm("mul.rn.f32x2 %0, %1, %2;" : "=l"(d) : "l"(a), "l"(b)); return d;
}
__device__ __forceinline__ u64 add2(u64 a, u64 b) {
    u64 d; asm("add.rn.f32x2 %0, %1, %2;" : "=l"(d) : "l"(a), "l"(b)); return d;
}

// ---------------- 32x32 bit-matrix transpose (warp) ----------------
__device__ __forceinline__ unsigned bittranspose(unsigned x, int lane) {
    const unsigned msk[5] = {0xFFFF0000u, 0xFF00FF00u, 0xF0F0F0F0u, 0xCCCCCCCCu, 0xAAAAAAAAu};
#pragma unroll
    for (int k = 0; k < 5; k++) {
        int s = 16 >> k;
        unsigned m = msk[k];
        unsigned y = __shfl_xor_sync(0xffffffffu, x, s);
        if ((lane & s) == 0) x = (x & ~m) | ((y << s) & m);
        else                 x = (x &  m) | ((y >> s) & ~m);
    }
    return x;
}

// ---------------- k1: triangular adjacency with mirror-transpose ----------------
// grid 1024 x 128 threads (4 warps). block b: pair p=b>>2, quarter qd=b&3.
// tiles tA=p, tB=511-p; warp w handles chunk residues (qd*4+w) mod 16.
// lane = row within tile; row constants (-2x,-2y,-2z,sq) packed in registers.
struct RowPack { u64 x2, y2, z2, s2; };

__device__ __forceinline__ RowPack load_rowpack(const float* __restrict__ pts, int r) {
    float x = pts[3*r], y = pts[3*r+1], z = pts[3*r+2];
    float s = __fadd_rn(__fadd_rn(__fmul_rn(x,x), __fmul_rn(y,y)), __fmul_rn(z,z));
    float xn = __fmul_rn(-2.0f, x);
    float yn = __fmul_rn(-2.0f, y);
    float zn = __fmul_rn(-2.0f, z);
    RowPack rp;
    rp.x2 = pack2(xn, xn); rp.y2 = pack2(yn, yn); rp.z2 = pack2(zn, zn); rp.s2 = pack2(s, s);
    return rp;
}

__device__ __forceinline__ unsigned tile_word(const RowPack& rp, const u64* __restrict__ sj,
                                              u64 negeps) {
    unsigned wrd = 0;
#pragma unroll
    for (int q = 0; q < 16; q++) {
        const u64* e = sj + q*4;
        u64 jx = e[0], jy = e[1], jz = e[2], js = e[3];
        u64 dotn = add2(add2(mul2(rp.x2, jx), mul2(rp.y2, jy)), mul2(rp.z2, jz));
        u64 d2   = add2(add2(rp.s2, js), dotn);
        u64 v    = add2(d2, negeps);          // sign bit <=> d2 < EPS2 (exact for strict <)
        unsigned lo, hi;
        asm("mov.b64 {%0, %1}, %2;" : "=r"(lo), "=r"(hi) : "l"(v));
        wrd |= (lo >> 31) << (2*q);
        wrd |= (hi >> 31) << (2*q + 1);
    }
    return wrd;
}

__global__ void __launch_bounds__(128) k1_adj(const float* __restrict__ pts) {
    __shared__ __align__(16) u64 sj[4][16][4];   // [warp][q][x2,y2,z2,s2]
    const int w    = threadIdx.x >> 5;
    const int lane = threadIdx.x & 31;
    const int p  = blockIdx.x >> 2;
    const int qd = blockIdx.x & 3;
    const int tA = p, tB = (NT - 1) - p;
    const u64 negeps = pack2(-EPS2, -EPS2);

    RowPack ra = load_rowpack(pts, tA*32 + lane);
    RowPack rb = load_rowpack(pts, tB*32 + lane);

    for (int jc = qd*4 + w; jc <= tB; jc += 16) {
        // ---- stage 32 j points as packed pairs (lanes 0..15, 2 points each) ----
        if (lane < 16) {
            int j0 = jc*32 + 2*lane;
            const float2* pp = (const float2*)(pts + 3*j0);
            float2 a = pp[0], b = pp[1], c = pp[2];
            // x0=a.x y0=a.y z0=b.x | x1=b.y y1=c.x z1=c.y
            float s0 = __fadd_rn(__fadd_rn(__fmul_rn(a.x,a.x), __fmul_rn(a.y,a.y)), __fmul_rn(b.x,b.x));
            float s1 = __fadd_rn(__fadd_rn(__fmul_rn(b.y,b.y), __fmul_rn(c.x,c.x)), __fmul_rn(c.y,c.y));
            u64* dst = sj[w][lane];
            dst[0] = pack2(a.x, b.y);
            dst[1] = pack2(a.y, c.x);
            dst[2] = pack2(b.x, c.y);
            dst[3] = pack2(s0, s1);
        }
        __syncwarp();

        unsigned wB = tile_word(rb, &sj[w][0][0], negeps);
        g_adj[(((tB << 9) + jc) << 5) + lane] = wB;
        if (jc < tB) {
            unsigned tw = bittranspose(wB, lane);
            g_adj[(((jc << 9) + tB) << 5) + lane] = tw;
        }
        if (jc <= tA) {
            unsigned wA = tile_word(ra, &sj[w][0][0], negeps);
            g_adj[(((tA << 9) + jc) << 5) + lane] = wA;
            if (jc < tA) {
                unsigned tw = bittranspose(wA, lane);
                g_adj[(((jc << 9) + tA) << 5) + lane] = tw;
            }
        }
        __syncwarp();
    }
}

// ---------------- k1b: degree/core + init (MLP-8 popc pass) ----------------
__global__ void __launch_bounds__(256) k1b_deg() {
    __shared__ int part[8][32];
    int rt = blockIdx.x;
    int lane = threadIdx.x & 31, sl = threadIdx.x >> 5;
    const unsigned* basep = g_adj + ((size_t)rt << 14);
    int cnt = 0;
    for (int wi0 = sl; wi0 < NW; wi0 += 64) {
        unsigned wb[8];
#pragma unroll
        for (int u = 0; u < 8; u++) wb[u] = basep[((wi0 + u*8) << 5) + lane];
#pragma unroll
        for (int u = 0; u < 8; u++) cnt += __popc(wb[u]);
    }
    part[sl][lane] = cnt;
    __syncthreads();
    if (threadIdx.x < 32) {
        int deg = 0;
#pragma unroll
        for (int s = 0; s < 8; s++) deg += part[s][lane];
        int row = (rt << 5) + lane;
        int c = (deg >= MINPTS) ? 1 : 0;
        g_core[row]   = c;
        g_parent[row] = row;
        unsigned cb = __ballot_sync(0xffffffffu, c != 0);
        if (lane == 0) g_corebits[rt] = cb;
    }
}

// ---------------- union-find (hook larger root under smaller =>
//                  final root of each component is its minimum index) ----------------
__device__ __forceinline__ int pload(int x) { return __ldcg(&g_parent[x]); }  // L2-coherent

__device__ __forceinline__ int uf_find(int x) {
    int pr = pload(x);
    while (pr != x) {
        int gp = pload(pr);
        if (gp != pr) g_parent[x] = gp;   // path halving; benign race
        x = pr;
        pr = gp;
    }
    return pr;
}

__device__ __forceinline__ void uf_union(int a, int b) {
    int ra = uf_find(a), rb = uf_find(b);
    while (ra != rb) {
        if (ra > rb) { int t = ra; ra = rb; rb = t; }
        int old = atomicCAS(&g_parent[rb], rb, ra);
        if (old == rb) return;
        rb = uf_find(old);
        ra = uf_find(ra);
    }
}

// ---------------- k2: unions over core-core edges (strictly lower triangle) ----------------
__global__ void __launch_bounds__(256) k2_union() {
    __shared__ unsigned scb[NW];
    int lane = threadIdx.x & 31, sl = threadIdx.x >> 5;
    for (int i = threadIdx.x; i < NW; i += 256) scb[i] = g_corebits[i];
    __syncthreads();

    int rt = (NT - 1) - blockIdx.x;          // biggest row-tiles first
    int row = (rt << 5) + lane;
    if (!g_core[row]) return;
    const unsigned* basep = g_adj + ((size_t)rt << 14);
    for (int wi0 = sl; wi0 <= rt; wi0 += 64) {
        unsigned wb[8];
#pragma unroll
        for (int u = 0; u < 8; u++) {
            int wi = wi0 + u*8;
            wb[u] = (wi <= rt) ? (basep[(wi << 5) + lane] & scb[wi]) : 0u;
        }
#pragma unroll
        for (int u = 0; u < 8; u++) {
            int wi = wi0 + u*8;
            unsigned word = wb[u];
            if (wi == rt) word &= (1u << lane) - 1u;   // j < row on diagonal tile
            while (word) {
                int b = __ffs(word) - 1;
                word &= word - 1u;
                uf_union(row, (wi << 5) + b);
            }
        }
    }
}

// ---------------- k4: flatten labels to u16 (root == component min < 16384) ----------------
__global__ void k4_flat() {
    int i = blockIdx.x * blockDim.x + threadIdx.x;
    if (i >= NPTS) return;
    g_lab16[i] = g_core[i] ? (unsigned short)uf_find(i) : (unsigned short)0xFFFF;
}

// ---------------- k5: per-point min label among core neighbors (smem table) ----------------
__global__ void __launch_bounds__(256) k5_border() {
    __shared__ unsigned short slab[NPTS];    // 32 KB flattened labels
    __shared__ unsigned scb[NW];
    __shared__ int part[8][32];
    int lane = threadIdx.x & 31, sl = threadIdx.x >> 5;

    {   // stage labels (coalesced uint4) + corebits
        const uint4* src = (const uint4*)g_lab16;
        uint4* dst = (uint4*)slab;
        for (int i = threadIdx.x; i < NPTS/8; i += 256) dst[i] = src[i];
        for (int i = threadIdx.x; i < NW; i += 256) scb[i] = g_corebits[i];
    }
    __syncthreads();

    int rt = blockIdx.x;
    const unsigned* basep = g_adj + ((size_t)rt << 14);
    int mn = 0xFFFF;
    for (int wi0 = sl; wi0 < NW; wi0 += 64) {
        unsigned wb[8];
#pragma unroll
        for (int u = 0; u < 8; u++) wb[u] = basep[((wi0 + u*8) << 5) + lane];
#pragma unroll
        for (int u = 0; u < 8; u++) {
            unsigned word = wb[u] & scb[wi0 + u*8];
            int jb = (wi0 + u*8) << 5;
            while (word) {
                int b = __ffs(word) - 1;
                word &= word - 1u;
                mn = min(mn, (int)slab[jb + b]);
            }
        }
    }
    part[sl][lane] = mn;
    __syncthreads();
    if (threadIdx.x < 32) {
        int m = part[0][lane];
#pragma unroll
        for (int s = 1; s < 8; s++) m = min(m, part[s][lane]);
        g_root[(rt << 5) + lane] = (m == 0xFFFF) ? BIGV : m;
    }
}

// ---------------- k6: rank scan (renumber roots) + final labels ----------------
__global__ void __launch_bounds__(512) k6_finish(float* __restrict__ out) {
    __shared__ int ssum[512];
    int t = threadIdx.x;                 // 512 threads x 32 elements
    int base = t * 32;
    int cnt = 0;
#pragma unroll
    for (int k = 0; k < 32; k++) {
        int i = base + k;
        cnt += (g_core[i] && g_parent[i] == i) ? 1 : 0;   // component root
    }
    ssum[t] = cnt;
    __syncthreads();
    for (int o = 1; o < 512; o <<= 1) {
        int v = (t >= o) ? ssum[t - o] : 0;
        __syncthreads();
        ssum[t] += v;
        __syncthreads();
    }
    int run = (t > 0) ? ssum[t - 1] : 0;
#pragma unroll
    for (int k = 0; k < 32; k++) {
        int i = base + k;
        run += (g_core[i] && g_parent[i] == i) ? 1 : 0;
        g_rank[i] = run - 1;             // inclusive cumsum - 1
    }
    __syncthreads();
#pragma unroll
    for (int k = 0; k < 32; k++) {
        int i = base + k;
        int r = g_root[i];
        out[i] = (r < BIGV) ? (float)g_rank[r] : -1.0f;
    }
}

// ---------------- launch ----------------
extern "C" void kernel_launch(void* const* d_in, const int* in_sizes, int n_in,
                              void* d_out, int out_size) {
    const float* pts = (const float*)d_in[0];
    float* out = (float*)d_out;
    (void)in_sizes; (void)n_in; (void)out_size;

    k1_adj    <<<NT * 2, 128>>>(pts);    // 1024 blocks: pair quarters
    k1b_deg   <<<NT, 256>>>();
    k2_union  <<<NT, 256>>>();
    k4_flat   <<<NPTS / 256, 256>>>();
    k5_border <<<NT, 256>>>();
    k6_finish <<<1, 512>>>(out);
}